// round 15
// baseline (speedup 1.0000x reference)
#include <cuda_runtime.h>

#define N_NODES 100000
#define N_EDGES 1600000
#define DIM 128
#define HID 16
#define NCLS 40
#define BN_EPS 1e-5f

typedef unsigned long long ull;

// ---------------- f32x2 packed-math helpers (B300 FFMA2 path) --------------
__device__ __forceinline__ ull pack2(float x, float y) {
    ull r; asm("mov.b64 %0,{%1,%2};" : "=l"(r) : "f"(x), "f"(y)); return r;
}
__device__ __forceinline__ void unpack2(ull v, float& x, float& y) {
    asm("mov.b64 {%0,%1},%2;" : "=f"(x), "=f"(y) : "l"(v));
}
__device__ __forceinline__ ull fma2(ull a, ull b, ull c) {
    ull d; asm("fma.rn.f32x2 %0,%1,%2,%3;" : "=l"(d) : "l"(a), "l"(b), "l"(c)); return d;
}
__device__ __forceinline__ ull add2(ull a, ull b) {
    ull d; asm("add.rn.f32x2 %0,%1,%2;" : "=l"(d) : "l"(a), "l"(b)); return d;
}
__device__ __forceinline__ ull shfl2(ull v, int src) {
    float lo, hi; unpack2(v, lo, hi);
    lo = __shfl_sync(0xffffffffu, lo, src);
    hi = __shfl_sync(0xffffffffu, hi, src);
    return pack2(lo, hi);
}

// ---------------- scratch (static device globals) ---------------------------
__device__ float  g_h1[N_NODES * HID];
__device__ float  g_s1[N_NODES * HID];
__device__ float  g_agg[N_NODES * HID];
__device__ double g_M3[3][HID * HID];
__device__ double g_sum3[3][HID];
__device__ float  g_scale3[3][DIM];
__device__ float  g_shift3[3][DIM];
__device__ unsigned int g_cnt3[3];
__device__ int    g_row_ptr[N_NODES + 1];

#define TB 256
#define NODE_BLK ((N_NODES + TB - 1) / TB)          // 391
#define RP_BLK   ((N_NODES + 1 + TB - 1) / TB)      // 391
#define SPMM_BLK ((N_NODES + 31) / 32)              // 3125 (R4 core: 8 thr/row)
#define N_PAIRS  (N_NODES / 2)                      // 50000
#define STATS_BLK 592                               // stats-spmm (v3 core, strided)

// ---------------- fused: row_ptr build + stats zero + x@W1 ------------------
__global__ void prolog_kernel(const int* __restrict__ row, const float* __restrict__ x,
                              const float* __restrict__ W, float* __restrict__ y) {
    if (blockIdx.x >= NODE_BLK) {
        int t = threadIdx.x;
        if (blockIdx.x == NODE_BLK) {
            if (t < HID * HID) { g_M3[0][t] = 0.0; g_M3[1][t] = 0.0; g_M3[2][t] = 0.0; }
            if (t < HID) { g_sum3[0][t] = 0.0; g_sum3[1][t] = 0.0; g_sum3[2][t] = 0.0; }
            if (t < 3) g_cnt3[t] = 0u;
        }
        int i = (blockIdx.x - NODE_BLK) * TB + t;
        if (i > N_NODES) return;
        int lo = 0, hi = N_EDGES;
        while (lo < hi) {
            int mid = (lo + hi) >> 1;
            if (row[mid] < i) lo = mid + 1; else hi = mid;
        }
        g_row_ptr[i] = lo;
        return;
    }
    __shared__ __align__(16) float Ws[DIM * HID];
    for (int i = threadIdx.x; i < DIM * HID; i += TB) Ws[i] = W[i];
    __syncthreads();
    int n = blockIdx.x * TB + threadIdx.x;
    if (n >= N_NODES) return;
    ull acc2[8];
    #pragma unroll
    for (int j = 0; j < 8; j++) acc2[j] = 0ull;
    const float4* xr = reinterpret_cast<const float4*>(x + (size_t)n * DIM);
    #pragma unroll 4
    for (int d4 = 0; d4 < DIM / 4; d4++) {
        float4 xv = xr[d4];
        #pragma unroll
        for (int dd = 0; dd < 4; dd++) {
            float xd = (&xv.x)[dd];
            ull xb = pack2(xd, xd);
            const ulonglong2* wr = reinterpret_cast<const ulonglong2*>(&Ws[(d4 * 4 + dd) * HID]);
            #pragma unroll
            for (int p = 0; p < 4; p++) {
                ulonglong2 w = wr[p];
                acc2[p * 2 + 0] = fma2(xb, w.x, acc2[p * 2 + 0]);
                acc2[p * 2 + 1] = fma2(xb, w.y, acc2[p * 2 + 1]);
            }
        }
    }
    ull* yr = reinterpret_cast<ull*>(y + (size_t)n * HID);
    #pragma unroll
    for (int j = 0; j < 8; j++) yr[j] = acc2[j];
}

// ---------------- 16-wide SpMM (R4 core): 8 threads/row, two quads ----------
template<bool RELU>
__global__ void spmm16(const float4* __restrict__ h, const float* __restrict__ vals,
                       const int* __restrict__ col, const float4* __restrict__ bias4,
                       float4* __restrict__ out) {
    int t = threadIdx.x;
    int q = t & 3;
    int sub = (t >> 2) & 1;
    int r = blockIdx.x * 32 + (t >> 3);
    if (r >= N_NODES) return;
    int e0 = g_row_ptr[r], e1 = g_row_ptr[r + 1];
    float4 acc = make_float4(0.f, 0.f, 0.f, 0.f);
    int e = e0 + sub * 4;
    while (e + 4 <= e1) {
        int   c0 = col[e],     c1 = col[e + 1],  c2 = col[e + 2],  c3 = col[e + 3];
        float v0 = vals[e],    v1 = vals[e + 1], v2 = vals[e + 2], v3 = vals[e + 3];
        float4 h0 = h[(size_t)c0 * 4 + q];
        float4 h1 = h[(size_t)c1 * 4 + q];
        float4 h2 = h[(size_t)c2 * 4 + q];
        float4 h3 = h[(size_t)c3 * 4 + q];
        acc.x += v0 * h0.x; acc.y += v0 * h0.y; acc.z += v0 * h0.z; acc.w += v0 * h0.w;
        acc.x += v1 * h1.x; acc.y += v1 * h1.y; acc.z += v1 * h1.z; acc.w += v1 * h1.w;
        acc.x += v2 * h2.x; acc.y += v2 * h2.y; acc.z += v2 * h2.z; acc.w += v2 * h2.w;
        acc.x += v3 * h3.x; acc.y += v3 * h3.y; acc.z += v3 * h3.z; acc.w += v3 * h3.w;
        e += 8;
    }
    int eend = min(e + 4, e1);
    for (; e < eend; e++) {
        float v = vals[e];
        float4 hv = h[(size_t)col[e] * 4 + q];
        acc.x += v * hv.x; acc.y += v * hv.y; acc.z += v * hv.z; acc.w += v * hv.w;
    }
    acc.x += __shfl_xor_sync(0xffffffffu, acc.x, 4);
    acc.y += __shfl_xor_sync(0xffffffffu, acc.y, 4);
    acc.z += __shfl_xor_sync(0xffffffffu, acc.z, 4);
    acc.w += __shfl_xor_sync(0xffffffffu, acc.w, 4);
    if (sub == 0) {
        if (RELU) {
            float4 b = bias4[q];
            acc.x = fmaxf(acc.x + b.x, 0.f);
            acc.y = fmaxf(acc.y + b.y, 0.f);
            acc.z = fmaxf(acc.z + b.z, 0.f);
            acc.w = fmaxf(acc.w + b.w, 0.f);
        }
        out[(size_t)r * 4 + q] = acc;
    }
}

// ---------------- stats-fused SpMM (R12-proven): warp per row pair ----------
// v3 core (q=lane&7 float2, sub=lane>>3); strided over pairs; fuses BN
// sufficient statistics in registers; LAST block computes BN affine.
__global__ void spmm16_stats(const float* __restrict__ h, const float* __restrict__ vals,
                             const int* __restrict__ col, float* __restrict__ out,
                             double* __restrict__ gM, double* __restrict__ gSum,
                             const float* __restrict__ W2,
                             const float* __restrict__ gamma,
                             const float* __restrict__ beta,
                             float* __restrict__ gScale, float* __restrict__ gShift,
                             unsigned int* __restrict__ cnt) {
    __shared__ float sM[HID * HID];
    __shared__ float sSum[HID];
    int t = threadIdx.x;
    if (t < HID * HID) sM[t] = 0.f;
    if (t < HID) sSum[t] = 0.f;
    __syncthreads();
    int lane = t & 31;
    int warp = t >> 5;
    int q = lane & 7;
    int sub = lane >> 3;
    const ull* h8 = reinterpret_cast<const ull*>(h);

    ull mAcc[4];
    ull sumAcc = 0ull;
    #pragma unroll
    for (int s = 0; s < 4; s++) mAcc[s] = 0ull;

    for (int p = blockIdx.x * 8 + warp; p < N_PAIRS; p += STATS_BLK * 8) {
        int r0 = p * 2;
        int a0 = g_row_ptr[r0];
        int a1 = g_row_ptr[r0 + 1];
        int a2 = g_row_ptr[r0 + 2];
        int len = a2 - a0;
        ull accA = 0ull, accB = 0ull;
        for (int off = sub * 8; off < len; off += 32) {
            #pragma unroll
            for (int i = 0; i < 8; i++) {
                int o = off + i;
                bool valid = (o < len);
                int idx = valid ? (a0 + o) : (a2 - 1);
                float v = vals[idx];
                if (!valid) v = 0.f;
                int c = col[idx];
                ull hv = h8[(size_t)c * 8 + q];
                float vA = ((a0 + o) < a1) ? v : 0.f;
                float vB = v - vA;
                accA = fma2(pack2(vA, vA), hv, accA);
                accB = fma2(pack2(vB, vB), hv, accB);
            }
        }
        accA = add2(accA, __shfl_xor_sync(0xffffffffu, accA, 8));
        accA = add2(accA, __shfl_xor_sync(0xffffffffu, accA, 16));
        accB = add2(accB, __shfl_xor_sync(0xffffffffu, accB, 8));
        accB = add2(accB, __shfl_xor_sync(0xffffffffu, accB, 16));
        if (sub == 0) {
            float x0, x1, y0, y1;
            unpack2(accA, x0, x1);
            unpack2(accB, y0, y1);
            float2* o2 = reinterpret_cast<float2*>(out);
            o2[(size_t)r0 * 8 + q]       = make_float2(x0, x1);
            o2[(size_t)(r0 + 1) * 8 + q] = make_float2(y0, y1);
        }
        // stats: every lane holds the reduced float2 for its q
        sumAcc = add2(sumAcc, add2(accA, accB));
        int srcj = lane >> 2;               // lane holding float2 containing a[j]
        int klane = (lane & 1) * 4;         // lanes holding the 4 k-float2s
        ull ja2 = shfl2(accA, srcj);
        ull jb2 = shfl2(accB, srcj);
        float jlA, jhA, jlB, jhB;
        unpack2(ja2, jlA, jhA);
        unpack2(jb2, jlB, jhB);
        float ajA = (lane & 2) ? jhA : jlA;
        float ajB = (lane & 2) ? jhB : jlB;
        ull ajA2 = pack2(ajA, ajA);
        ull ajB2 = pack2(ajB, ajB);
        #pragma unroll
        for (int s = 0; s < 4; s++) {
            ull kA = shfl2(accA, klane + s);
            ull kB = shfl2(accB, klane + s);
            mAcc[s] = fma2(ajA2, kA, mAcc[s]);
            mAcc[s] = fma2(ajB2, kB, mAcc[s]);
        }
    }
    {
        int j = lane >> 1;
        int k0 = (lane & 1) * 8;
        #pragma unroll
        for (int s = 0; s < 4; s++) {
            float lo, hi;
            unpack2(mAcc[s], lo, hi);
            atomicAdd(&sM[j * HID + k0 + 2 * s],     lo);
            atomicAdd(&sM[j * HID + k0 + 2 * s + 1], hi);
        }
        if (sub == 0) {
            float lo, hi;
            unpack2(sumAcc, lo, hi);
            atomicAdd(&sSum[2 * q],     lo);
            atomicAdd(&sSum[2 * q + 1], hi);
        }
        __syncthreads();
        if (t < HID * HID) atomicAdd(&gM[t], (double)sM[t]);
        if (t < HID) atomicAdd(&gSum[t], (double)sSum[t]);
    }
    // ---- last block computes BN affine ----
    __threadfence();
    __shared__ unsigned int sIsLast;
    if (t == 0) sIsLast = (atomicAdd(cnt, 1u) == STATS_BLK - 1) ? 1u : 0u;
    __syncthreads();
    if (!sIsLast) return;
    __shared__ double Ss[HID];
    if (t < HID) Ss[t] = gSum[t];
    __syncthreads();
    const double invN = 1.0 / (double)N_NODES;
    {
        int j2 = t >> 4, k2 = t & 15;
        sM[t] = (float)(gM[t] - Ss[j2] * Ss[k2] * invN);   // centered, fp32
    }
    __syncthreads();
    if (t < DIM) {
        float wf[HID];
        #pragma unroll
        for (int kk = 0; kk < HID; kk++) wf[kk] = W2[kk * DIM + t];
        double sn = 0.0;
        #pragma unroll
        for (int kk = 0; kk < HID; kk++) sn += Ss[kk] * (double)wf[kk];
        sn *= invN;
        float q0 = 0.f, q1 = 0.f, q2 = 0.f, q3 = 0.f;
        #pragma unroll
        for (int a = 0; a < HID; a++) {
            float wa = wf[a];
            #pragma unroll
            for (int b = 0; b < HID; b += 4) {
                q0 += sM[a * HID + b + 0] * (wa * wf[b + 0]);
                q1 += sM[a * HID + b + 1] * (wa * wf[b + 1]);
                q2 += sM[a * HID + b + 2] * (wa * wf[b + 2]);
                q3 += sM[a * HID + b + 3] * (wa * wf[b + 3]);
            }
        }
        float var = ((q0 + q1) + (q2 + q3)) * (float)invN;
        float scale = rsqrtf(fmaxf(var, 0.f) + BN_EPS) * gamma[t];
        gScale[t] = scale;
        gShift[t] = beta[t] - (float)sn * scale;   // b2 cancels in (h2-mean)
    }
}

// ---------------- fused: h1 = relu(bn(agg@W2)) @ W1next  (lean, f32x2) ------
__global__ void fused_bn_gemm(const float* __restrict__ agg, const float* __restrict__ W2,
                              const float* __restrict__ W1n,
                              const float* __restrict__ gScale,
                              const float* __restrict__ gShift,
                              float* __restrict__ y) {
    __shared__ __align__(16) float W2s[HID * DIM];
    __shared__ __align__(16) float W1s[DIM * HID];
    __shared__ __align__(16) float scl[DIM];
    __shared__ __align__(16) float sft[DIM];
    for (int i = threadIdx.x; i < HID * DIM; i += TB) {
        W2s[i] = W2[i];
        W1s[i] = W1n[i];
    }
    for (int i = threadIdx.x; i < DIM; i += TB) {
        scl[i] = gScale[i];
        sft[i] = gShift[i];
    }
    __syncthreads();
    int n = blockIdx.x * TB + threadIdx.x;
    if (n >= N_NODES) return;
    ull a2[HID];
    {
        const float4* ar = reinterpret_cast<const float4*>(agg + (size_t)n * HID);
        #pragma unroll
        for (int k4 = 0; k4 < 4; k4++) {
            float4 v = ar[k4];
            a2[k4*4+0] = pack2(v.x, v.x);
            a2[k4*4+1] = pack2(v.y, v.y);
            a2[k4*4+2] = pack2(v.z, v.z);
            a2[k4*4+3] = pack2(v.w, v.w);
        }
    }
    ull acc2[8];
    #pragma unroll
    for (int j = 0; j < 8; j++) acc2[j] = 0ull;
    #pragma unroll 2
    for (int cb = 0; cb < DIM; cb += 4) {
        ull t01 = 0ull, t23 = 0ull;
        const ulonglong2* w2p = reinterpret_cast<const ulonglong2*>(&W2s[cb]);
        #pragma unroll
        for (int k = 0; k < HID; k++) {
            ulonglong2 w = w2p[k * (DIM / 4)];
            t01 = fma2(a2[k], w.x, t01);
            t23 = fma2(a2[k], w.y, t23);
        }
        ulonglong2 sc = *reinterpret_cast<const ulonglong2*>(&scl[cb]);
        ulonglong2 sf = *reinterpret_cast<const ulonglong2*>(&sft[cb]);
        t01 = fma2(t01, sc.x, sf.x);
        t23 = fma2(t23, sc.y, sf.y);
        float v0, v1, v2, v3;
        unpack2(t01, v0, v1);
        unpack2(t23, v2, v3);
        v0 = fmaxf(v0, 0.f); v1 = fmaxf(v1, 0.f);
        v2 = fmaxf(v2, 0.f); v3 = fmaxf(v3, 0.f);
        ull vb[4] = { pack2(v0, v0), pack2(v1, v1), pack2(v2, v2), pack2(v3, v3) };
        #pragma unroll
        for (int c = 0; c < 4; c++) {
            const ulonglong2* w1p = reinterpret_cast<const ulonglong2*>(&W1s[(cb + c) * HID]);
            #pragma unroll
            for (int p = 0; p < 4; p++) {
                ulonglong2 w = w1p[p];
                acc2[p * 2 + 0] = fma2(vb[c], w.x, acc2[p * 2 + 0]);
                acc2[p * 2 + 1] = fma2(vb[c], w.y, acc2[p * 2 + 1]);
            }
        }
    }
    ull* yr = reinterpret_cast<ull*>(y + (size_t)n * HID);
    #pragma unroll
    for (int j = 0; j < 8; j++) yr[j] = acc2[j];
}

// ---------------- out[N,40] = agg[N,16] @ W[16,40] + b  (f32x2 packed) ------
__global__ void out_gemm(const float* __restrict__ agg, const float* __restrict__ W,
                         const float* __restrict__ b, float* __restrict__ out) {
    __shared__ __align__(16) float Ws[HID * NCLS];
    __shared__ __align__(16) float bs[NCLS];
    for (int i = threadIdx.x; i < HID * NCLS; i += TB) Ws[i] = W[i];
    if (threadIdx.x < NCLS) bs[threadIdx.x] = b[threadIdx.x];
    __syncthreads();
    int n = blockIdx.x * TB + threadIdx.x;
    if (n >= N_NODES) return;
    ull a2[HID];
    {
        const float4* ar = reinterpret_cast<const float4*>(agg + (size_t)n * HID);
        #pragma unroll
        for (int k4 = 0; k4 < 4; k4++) {
            float4 v = ar[k4];
            a2[k4*4+0] = pack2(v.x, v.x);
            a2[k4*4+1] = pack2(v.y, v.y);
            a2[k4*4+2] = pack2(v.z, v.z);
            a2[k4*4+3] = pack2(v.w, v.w);
        }
    }
    ull o2[NCLS / 2];
    const ull* bp = reinterpret_cast<const ull*>(bs);
    #pragma unroll
    for (int p = 0; p < NCLS / 2; p++) o2[p] = bp[p];
    #pragma unroll
    for (int k = 0; k < HID; k++) {
        const ull* wr = reinterpret_cast<const ull*>(&Ws[k * NCLS]);
        #pragma unroll
        for (int p = 0; p < NCLS / 2; p++)
            o2[p] = fma2(a2[k], wr[p], o2[p]);
    }
    ull* orow = reinterpret_cast<ull*>(out + (size_t)n * NCLS);
    #pragma unroll
    for (int p = 0; p < NCLS / 2; p++) orow[p] = o2[p];
}

// ============================================================================
extern "C" void kernel_launch(void* const* d_in, const int* in_sizes, int n_in,
                              void* d_out, int out_size) {
    const float* x     = (const float*)d_in[0];
    const float* vals  = (const float*)d_in[1];
    const float* W1    = (const float*)d_in[2];   // (3,128,16)
    const float* b1    = (const float*)d_in[3];   // (3,16)
    const float* W2    = (const float*)d_in[4];   // (3,16,128)
    const float* gamma = (const float*)d_in[6];   // (3,128)
    const float* beta  = (const float*)d_in[7];   // (3,128)
    const float* W1f   = (const float*)d_in[8];   // (128,16)
    const float* b1f   = (const float*)d_in[9];   // (16,)
    const float* W2f   = (const float*)d_in[10];  // (16,40)
    const float* b2f   = (const float*)d_in[11];  // (40,)
    const int*   row   = (const int*)d_in[12];
    const int*   col   = (const int*)d_in[13];
    float* out = (float*)d_out;
    // d_in[5] (b2) cancels inside batchnorm.

    float *p_h1, *p_s1, *p_agg, *p_scale3, *p_shift3;
    double *p_M3, *p_sum3;
    unsigned int* p_cnt3;
    cudaGetSymbolAddress((void**)&p_h1,     g_h1);
    cudaGetSymbolAddress((void**)&p_s1,     g_s1);
    cudaGetSymbolAddress((void**)&p_agg,    g_agg);
    cudaGetSymbolAddress((void**)&p_M3,     g_M3);
    cudaGetSymbolAddress((void**)&p_sum3,   g_sum3);
    cudaGetSymbolAddress((void**)&p_scale3, g_scale3);
    cudaGetSymbolAddress((void**)&p_shift3, g_shift3);
    cudaGetSymbolAddress((void**)&p_cnt3,   g_cnt3);

    prolog_kernel<<<NODE_BLK + RP_BLK, TB>>>(row, x, W1, p_h1);

    for (int i = 0; i < 3; i++) {
        double* gM = p_M3 + (size_t)i * HID * HID;
        double* gS = p_sum3 + (size_t)i * HID;
        float* gScale = p_scale3 + (size_t)i * DIM;
        float* gShift = p_shift3 + (size_t)i * DIM;
        const float* W2L = W2 + (size_t)i * HID * DIM;
        const float* Wnext = (i < 2) ? (W1 + (size_t)(i + 1) * DIM * HID) : W1f;

        spmm16<true><<<SPMM_BLK, TB>>>((const float4*)p_h1, vals, col,
                                       (const float4*)(b1 + i * HID), (float4*)p_s1);
        spmm16_stats<<<STATS_BLK, TB>>>(p_s1, vals, col, p_agg, gM, gS, W2L,
                                        gamma + i * DIM, beta + i * DIM,
                                        gScale, gShift, p_cnt3 + i);
        fused_bn_gemm<<<NODE_BLK, TB>>>(p_agg, W2L, Wnext, gScale, gShift, p_h1);
    }

    spmm16<true><<<SPMM_BLK, TB>>>((const float4*)p_h1, vals, col,
                                   (const float4*)b1f, (float4*)p_s1);
    spmm16<false><<<SPMM_BLK, TB>>>((const float4*)p_s1, vals, col,
                                    nullptr, (float4*)p_agg);
    out_gemm<<<NODE_BLK, TB>>>(p_agg, W2f, b2f, out);
}

// round 16
// speedup vs baseline: 1.1028x; 1.1028x over previous
#include <cuda_runtime.h>

#define N_NODES 100000
#define N_EDGES 1600000
#define DIM 128
#define HID 16
#define NCLS 40
#define BN_EPS 1e-5f

typedef unsigned long long ull;

// ---------------- f32x2 packed-math helpers (B300 FFMA2 path) --------------
__device__ __forceinline__ ull pack2(float x, float y) {
    ull r; asm("mov.b64 %0,{%1,%2};" : "=l"(r) : "f"(x), "f"(y)); return r;
}
__device__ __forceinline__ void unpack2(ull v, float& x, float& y) {
    asm("mov.b64 {%0,%1},%2;" : "=f"(x), "=f"(y) : "l"(v));
}
__device__ __forceinline__ ull fma2(ull a, ull b, ull c) {
    ull d; asm("fma.rn.f32x2 %0,%1,%2,%3;" : "=l"(d) : "l"(a), "l"(b), "l"(c)); return d;
}

// ---------------- scratch (static device globals) ---------------------------
__device__ float  g_h1[N_NODES * HID];
__device__ float  g_s1[N_NODES * HID];
__device__ float  g_agg[N_NODES * HID];
__device__ double g_sum16[HID];
__device__ double g_M[HID * HID];
__device__ float  g_scale[DIM];
__device__ float  g_shift[DIM];
__device__ int    g_row_ptr[N_NODES + 1];
__device__ unsigned int g_cnt = 0;

#define TB 256
#define NODE_BLK ((N_NODES + TB - 1) / TB)          // 391
#define RP_BLK   ((N_NODES + 1 + TB - 1) / TB)      // 391
#define SPMM_BLK ((N_NODES + 31) / 32)              // 3125 (R4: 8 threads/row)
#define STATS_G  592
#define STATS_TILE 64
#define N_TILES  ((N_NODES + STATS_TILE - 1) / STATS_TILE)   // 1563

// ---------------- fused: row_ptr build + stats zero + x@W1 ------------------
__global__ void prolog_kernel(const int* __restrict__ row, const float* __restrict__ x,
                              const float* __restrict__ W, float* __restrict__ y) {
    if (blockIdx.x >= NODE_BLK) {
        int t = threadIdx.x;
        if (blockIdx.x == NODE_BLK) {   // zero stats accumulators (first layer)
            if (t < HID * HID) g_M[t] = 0.0;
            if (t < HID) g_sum16[t] = 0.0;
            if (t == 0) g_cnt = 0;
        }
        int i = (blockIdx.x - NODE_BLK) * TB + t;
        if (i > N_NODES) return;
        int lo = 0, hi = N_EDGES;
        while (lo < hi) {
            int mid = (lo + hi) >> 1;
            if (row[mid] < i) lo = mid + 1; else hi = mid;
        }
        g_row_ptr[i] = lo;
        return;
    }
    __shared__ __align__(16) float Ws[DIM * HID];
    for (int i = threadIdx.x; i < DIM * HID; i += TB) Ws[i] = W[i];
    __syncthreads();
    int n = blockIdx.x * TB + threadIdx.x;
    if (n >= N_NODES) return;
    ull acc2[8];
    #pragma unroll
    for (int j = 0; j < 8; j++) acc2[j] = 0ull;
    const float4* xr = reinterpret_cast<const float4*>(x + (size_t)n * DIM);
    #pragma unroll 4
    for (int d4 = 0; d4 < DIM / 4; d4++) {
        float4 xv = xr[d4];
        #pragma unroll
        for (int dd = 0; dd < 4; dd++) {
            float xd = (&xv.x)[dd];
            ull xb = pack2(xd, xd);
            const ulonglong2* wr = reinterpret_cast<const ulonglong2*>(&Ws[(d4 * 4 + dd) * HID]);
            #pragma unroll
            for (int p = 0; p < 4; p++) {
                ulonglong2 w = wr[p];
                acc2[p * 2 + 0] = fma2(xb, w.x, acc2[p * 2 + 0]);
                acc2[p * 2 + 1] = fma2(xb, w.y, acc2[p * 2 + 1]);
            }
        }
    }
    ull* yr = reinterpret_cast<ull*>(y + (size_t)n * HID);
    #pragma unroll
    for (int j = 0; j < 8; j++) yr[j] = acc2[j];
}

// ---------------- 16-wide SpMM (R4 core + SW pipeline): 8 threads/row -------
// lanes: q = lane&3 (float4 piece), sub = (lane>>2)&1 (edge-chunk phase).
// Next chunk's col/vals are prefetched while current gathers are in flight.
template<bool RELU>
__global__ void spmm16(const float4* __restrict__ h, const float* __restrict__ vals,
                       const int* __restrict__ col, const float4* __restrict__ bias4,
                       float4* __restrict__ out) {
    int t = threadIdx.x;
    int q = t & 3;
    int sub = (t >> 2) & 1;
    int r = blockIdx.x * 32 + (t >> 3);
    if (r >= N_NODES) return;
    int e0 = g_row_ptr[r], e1 = g_row_ptr[r + 1];
    float4 acc = make_float4(0.f, 0.f, 0.f, 0.f);
    int e = e0 + sub * 4;
    int   c0 = 0, c1 = 0, c2 = 0, c3 = 0;
    float v0 = 0.f, v1 = 0.f, v2 = 0.f, v3 = 0.f;
    bool have = (e + 4 <= e1);
    if (have) {
        c0 = col[e];     c1 = col[e + 1];  c2 = col[e + 2];  c3 = col[e + 3];
        v0 = vals[e];    v1 = vals[e + 1]; v2 = vals[e + 2]; v3 = vals[e + 3];
    }
    while (have) {
        // issue gathers for the current chunk
        float4 h0 = h[(size_t)c0 * 4 + q];
        float4 h1 = h[(size_t)c1 * 4 + q];
        float4 h2 = h[(size_t)c2 * 4 + q];
        float4 h3 = h[(size_t)c3 * 4 + q];
        // prefetch next chunk's indices/values while gathers are in flight
        int en = e + 8;
        bool haveN = (en + 4 <= e1);
        int   nc0 = 0, nc1 = 0, nc2 = 0, nc3 = 0;
        float nv0 = 0.f, nv1 = 0.f, nv2 = 0.f, nv3 = 0.f;
        if (haveN) {
            nc0 = col[en];     nc1 = col[en + 1];  nc2 = col[en + 2];  nc3 = col[en + 3];
            nv0 = vals[en];    nv1 = vals[en + 1]; nv2 = vals[en + 2]; nv3 = vals[en + 3];
        }
        acc.x += v0 * h0.x; acc.y += v0 * h0.y; acc.z += v0 * h0.z; acc.w += v0 * h0.w;
        acc.x += v1 * h1.x; acc.y += v1 * h1.y; acc.z += v1 * h1.z; acc.w += v1 * h1.w;
        acc.x += v2 * h2.x; acc.y += v2 * h2.y; acc.z += v2 * h2.z; acc.w += v2 * h2.w;
        acc.x += v3 * h3.x; acc.y += v3 * h3.y; acc.z += v3 * h3.z; acc.w += v3 * h3.w;
        e = en;
        have = haveN;
        c0 = nc0; c1 = nc1; c2 = nc2; c3 = nc3;
        v0 = nv0; v1 = nv1; v2 = nv2; v3 = nv3;
    }
    int eend = min(e + 4, e1);
    for (; e < eend; e++) {
        float v = vals[e];
        float4 hv = h[(size_t)col[e] * 4 + q];
        acc.x += v * hv.x; acc.y += v * hv.y; acc.z += v * hv.z; acc.w += v * hv.w;
    }
    // combine the two quads of this row (lanes l <-> l^4 share a row)
    acc.x += __shfl_xor_sync(0xffffffffu, acc.x, 4);
    acc.y += __shfl_xor_sync(0xffffffffu, acc.y, 4);
    acc.z += __shfl_xor_sync(0xffffffffu, acc.z, 4);
    acc.w += __shfl_xor_sync(0xffffffffu, acc.w, 4);
    if (sub == 0) {
        if (RELU) {
            float4 b = bias4[q];
            acc.x = fmaxf(acc.x + b.x, 0.f);
            acc.y = fmaxf(acc.y + b.y, 0.f);
            acc.z = fmaxf(acc.z + b.z, 0.f);
            acc.w = fmaxf(acc.w + b.w, 0.f);
        }
        out[(size_t)r * 4 + q] = acc;
    }
}

// ---------------- stats + BN prep (R7 variant): centered cov, fp32 epilogue -
__global__ void stats16_bn(const float* __restrict__ agg,
                           const float* __restrict__ W2,
                           const float* __restrict__ gamma,
                           const float* __restrict__ beta) {
    __shared__ __align__(16) float rows[STATS_TILE * HID];   // 4KB
    int t = threadIdx.x;
    int j = t >> 4, k = t & 15;
    float m0 = 0.f, m1 = 0.f, m2 = 0.f, m3 = 0.f;
    float s0 = 0.f, s1 = 0.f, s2 = 0.f, s3 = 0.f;
    for (int tile = blockIdx.x; tile < N_TILES; tile += STATS_G) {
        int r0 = tile * STATS_TILE;
        int nr = min(STATS_TILE, N_NODES - r0);
        __syncthreads();
        if (t < nr * 4)
            reinterpret_cast<float4*>(rows)[t] =
                reinterpret_cast<const float4*>(agg + (size_t)r0 * HID)[t];
        __syncthreads();
        #pragma unroll 2
        for (int rr = 0; rr + 4 <= nr; rr += 4) {
            float aj0 = rows[(rr + 0) * HID + j], ak0 = rows[(rr + 0) * HID + k];
            float aj1 = rows[(rr + 1) * HID + j], ak1 = rows[(rr + 1) * HID + k];
            float aj2 = rows[(rr + 2) * HID + j], ak2 = rows[(rr + 2) * HID + k];
            float aj3 = rows[(rr + 3) * HID + j], ak3 = rows[(rr + 3) * HID + k];
            m0 += aj0 * ak0; m1 += aj1 * ak1; m2 += aj2 * ak2; m3 += aj3 * ak3;
            if (j == 0) { s0 += ak0; s1 += ak1; s2 += ak2; s3 += ak3; }
        }
    }
    atomicAdd(&g_M[t], (double)((m0 + m1) + (m2 + m3)));
    if (j == 0) atomicAdd(&g_sum16[k], (double)((s0 + s1) + (s2 + s3)));

    // ---- last block computes BN affine ----
    __threadfence();
    __shared__ unsigned int sIsLast;
    if (t == 0) {
        unsigned int old = atomicAdd(&g_cnt, 1u);
        sIsLast = (old == gridDim.x - 1) ? 1u : 0u;
    }
    __syncthreads();
    if (!sIsLast) return;
    __shared__ float  Mc[HID * HID];
    __shared__ double Ss[HID];
    if (t < HID) Ss[t] = g_sum16[t];
    __syncthreads();
    const double invN = 1.0 / (double)N_NODES;
    {
        double m = g_M[t];
        Mc[t] = (float)(m - Ss[j] * Ss[k] * invN);
    }
    __syncthreads();
    if (t < DIM) {
        float wf[HID];
        #pragma unroll
        for (int kk = 0; kk < HID; kk++) wf[kk] = W2[kk * DIM + t];
        double sn = 0.0;
        #pragma unroll
        for (int kk = 0; kk < HID; kk++) sn += Ss[kk] * (double)wf[kk];
        sn *= invN;
        float q0 = 0.f, q1 = 0.f, q2 = 0.f, q3 = 0.f;
        #pragma unroll
        for (int a = 0; a < HID; a++) {
            float wa = wf[a];
            #pragma unroll
            for (int b = 0; b < HID; b += 4) {
                q0 += Mc[a * HID + b + 0] * (wa * wf[b + 0]);
                q1 += Mc[a * HID + b + 1] * (wa * wf[b + 1]);
                q2 += Mc[a * HID + b + 2] * (wa * wf[b + 2]);
                q3 += Mc[a * HID + b + 3] * (wa * wf[b + 3]);
            }
        }
        float var = ((q0 + q1) + (q2 + q3)) * (float)invN;
        float scale = rsqrtf(fmaxf(var, 0.f) + BN_EPS) * gamma[t];
        g_scale[t] = scale;
        g_shift[t] = beta[t] - (float)sn * scale;   // b2 cancels in (h2-mean)
    }
    __syncthreads();
    // reset accumulators for next layer (only last block runs this)
    g_M[t] = 0.0;
    if (t < HID) g_sum16[t] = 0.0;
    if (t == 0) g_cnt = 0;
}

// ---------------- fused: h1 = relu(bn(agg@W2)) @ W1next  (f32x2, R7) --------
__global__ void fused_bn_gemm(const float* __restrict__ agg, const float* __restrict__ W2,
                              const float* __restrict__ W1n, float* __restrict__ y) {
    __shared__ __align__(16) float W2s[HID * DIM];
    __shared__ __align__(16) float W1s[DIM * HID];
    __shared__ __align__(16) float scl[DIM];
    __shared__ __align__(16) float sft[DIM];
    for (int i = threadIdx.x; i < HID * DIM; i += TB) {
        W2s[i] = W2[i];
        W1s[i] = W1n[i];
    }
    for (int i = threadIdx.x; i < DIM; i += TB) {
        scl[i] = g_scale[i];
        sft[i] = g_shift[i];
    }
    __syncthreads();
    int n = blockIdx.x * TB + threadIdx.x;
    if (n >= N_NODES) return;
    ull a2[HID];
    {
        const float4* ar = reinterpret_cast<const float4*>(agg + (size_t)n * HID);
        #pragma unroll
        for (int k4 = 0; k4 < 4; k4++) {
            float4 v = ar[k4];
            a2[k4*4+0] = pack2(v.x, v.x);
            a2[k4*4+1] = pack2(v.y, v.y);
            a2[k4*4+2] = pack2(v.z, v.z);
            a2[k4*4+3] = pack2(v.w, v.w);
        }
    }
    ull acc2[8];
    #pragma unroll
    for (int j = 0; j < 8; j++) acc2[j] = 0ull;
    #pragma unroll 2
    for (int cb = 0; cb < DIM; cb += 4) {
        ull t01 = 0ull, t23 = 0ull;
        const ulonglong2* w2p = reinterpret_cast<const ulonglong2*>(&W2s[cb]);
        #pragma unroll
        for (int k = 0; k < HID; k++) {
            ulonglong2 w = w2p[k * (DIM / 4)];
            t01 = fma2(a2[k], w.x, t01);
            t23 = fma2(a2[k], w.y, t23);
        }
        ulonglong2 sc = *reinterpret_cast<const ulonglong2*>(&scl[cb]);
        ulonglong2 sf = *reinterpret_cast<const ulonglong2*>(&sft[cb]);
        t01 = fma2(t01, sc.x, sf.x);
        t23 = fma2(t23, sc.y, sf.y);
        float v0, v1, v2, v3;
        unpack2(t01, v0, v1);
        unpack2(t23, v2, v3);
        v0 = fmaxf(v0, 0.f); v1 = fmaxf(v1, 0.f);
        v2 = fmaxf(v2, 0.f); v3 = fmaxf(v3, 0.f);
        ull vb[4] = { pack2(v0, v0), pack2(v1, v1), pack2(v2, v2), pack2(v3, v3) };
        #pragma unroll
        for (int c = 0; c < 4; c++) {
            const ulonglong2* w1p = reinterpret_cast<const ulonglong2*>(&W1s[(cb + c) * HID]);
            #pragma unroll
            for (int p = 0; p < 4; p++) {
                ulonglong2 w = w1p[p];
                acc2[p * 2 + 0] = fma2(vb[c], w.x, acc2[p * 2 + 0]);
                acc2[p * 2 + 1] = fma2(vb[c], w.y, acc2[p * 2 + 1]);
            }
        }
    }
    ull* yr = reinterpret_cast<ull*>(y + (size_t)n * HID);
    #pragma unroll
    for (int j = 0; j < 8; j++) yr[j] = acc2[j];
}

// ---------------- out[N,40] = agg[N,16] @ W[16,40] + b  (f32x2 packed) ------
__global__ void out_gemm(const float* __restrict__ agg, const float* __restrict__ W,
                         const float* __restrict__ b, float* __restrict__ out) {
    __shared__ __align__(16) float Ws[HID * NCLS];
    __shared__ __align__(16) float bs[NCLS];
    for (int i = threadIdx.x; i < HID * NCLS; i += TB) Ws[i] = W[i];
    if (threadIdx.x < NCLS) bs[threadIdx.x] = b[threadIdx.x];
    __syncthreads();
    int n = blockIdx.x * TB + threadIdx.x;
    if (n >= N_NODES) return;
    ull a2[HID];
    {
        const float4* ar = reinterpret_cast<const float4*>(agg + (size_t)n * HID);
        #pragma unroll
        for (int k4 = 0; k4 < 4; k4++) {
            float4 v = ar[k4];
            a2[k4*4+0] = pack2(v.x, v.x);
            a2[k4*4+1] = pack2(v.y, v.y);
            a2[k4*4+2] = pack2(v.z, v.z);
            a2[k4*4+3] = pack2(v.w, v.w);
        }
    }
    ull o2[NCLS / 2];
    const ull* bp = reinterpret_cast<const ull*>(bs);
    #pragma unroll
    for (int p = 0; p < NCLS / 2; p++) o2[p] = bp[p];
    #pragma unroll
    for (int k = 0; k < HID; k++) {
        const ull* wr = reinterpret_cast<const ull*>(&Ws[k * NCLS]);
        #pragma unroll
        for (int p = 0; p < NCLS / 2; p++)
            o2[p] = fma2(a2[k], wr[p], o2[p]);
    }
    ull* orow = reinterpret_cast<ull*>(out + (size_t)n * NCLS);
    #pragma unroll
    for (int p = 0; p < NCLS / 2; p++) orow[p] = o2[p];
}

// ============================================================================
extern "C" void kernel_launch(void* const* d_in, const int* in_sizes, int n_in,
                              void* d_out, int out_size) {
    const float* x     = (const float*)d_in[0];
    const float* vals  = (const float*)d_in[1];
    const float* W1    = (const float*)d_in[2];   // (3,128,16)
    const float* b1    = (const float*)d_in[3];   // (3,16)
    const float* W2    = (const float*)d_in[4];   // (3,16,128)
    const float* gamma = (const float*)d_in[6];   // (3,128)
    const float* beta  = (const float*)d_in[7];   // (3,128)
    const float* W1f   = (const float*)d_in[8];   // (128,16)
    const float* b1f   = (const float*)d_in[9];   // (16,)
    const float* W2f   = (const float*)d_in[10];  // (16,40)
    const float* b2f   = (const float*)d_in[11];  // (40,)
    const int*   row   = (const int*)d_in[12];
    const int*   col   = (const int*)d_in[13];
    float* out = (float*)d_out;
    // d_in[5] (b2) cancels inside batchnorm.

    float *p_h1, *p_s1, *p_agg;
    cudaGetSymbolAddress((void**)&p_h1,  g_h1);
    cudaGetSymbolAddress((void**)&p_s1,  g_s1);
    cudaGetSymbolAddress((void**)&p_agg, g_agg);

    prolog_kernel<<<NODE_BLK + RP_BLK, TB>>>(row, x, W1, p_h1);

    for (int i = 0; i < 3; i++) {
        spmm16<true><<<SPMM_BLK, TB>>>((const float4*)p_h1, vals, col,
                                       (const float4*)(b1 + i * HID), (float4*)p_s1);
        spmm16<false><<<SPMM_BLK, TB>>>((const float4*)p_s1, vals, col,
                                        nullptr, (float4*)p_agg);
        stats16_bn<<<STATS_G, TB>>>(p_agg, W2 + (size_t)i * HID * DIM,
                                    gamma + i * DIM, beta + i * DIM);
        const float* Wnext = (i < 2) ? (W1 + (size_t)(i + 1) * DIM * HID) : W1f;
        fused_bn_gemm<<<NODE_BLK, TB>>>(p_agg, W2 + (size_t)i * HID * DIM, Wnext, p_h1);
    }

    spmm16<true><<<SPMM_BLK, TB>>>((const float4*)p_h1, vals, col,
                                   (const float4*)b1f, (float4*)p_s1);
    spmm16<false><<<SPMM_BLK, TB>>>((const float4*)p_s1, vals, col,
                                    nullptr, (float4*)p_agg);
    out_gemm<<<NODE_BLK, TB>>>(p_agg, W2f, b2f, out);
}

// round 17
// speedup vs baseline: 1.2106x; 1.0978x over previous
#include <cuda_runtime.h>

#define N_NODES 100000
#define N_EDGES 1600000
#define DIM 128
#define HID 16
#define NCLS 40
#define BN_EPS 1e-5f

typedef unsigned long long ull;

// ---------------- f32x2 packed-math helpers (B300 FFMA2 path) --------------
__device__ __forceinline__ ull pack2(float x, float y) {
    ull r; asm("mov.b64 %0,{%1,%2};" : "=l"(r) : "f"(x), "f"(y)); return r;
}
__device__ __forceinline__ void unpack2(ull v, float& x, float& y) {
    asm("mov.b64 {%0,%1},%2;" : "=f"(x), "=f"(y) : "l"(v));
}
__device__ __forceinline__ ull fma2(ull a, ull b, ull c) {
    ull d; asm("fma.rn.f32x2 %0,%1,%2,%3;" : "=l"(d) : "l"(a), "l"(b), "l"(c)); return d;
}

// ---------------- scratch (static device globals) ---------------------------
__device__ float  g_h1[N_NODES * HID];
__device__ float  g_s1[N_NODES * HID];
__device__ float  g_agg[N_NODES * HID];
__device__ double g_sum16[HID];
__device__ double g_M[HID * HID];
__device__ float  g_scale[DIM];
__device__ float  g_shift[DIM];
__device__ int    g_row_ptr[N_NODES + 1];
__device__ unsigned int g_cnt = 0;

#define TB 256
#define FTB 128
#define NODE_BLK ((N_NODES + TB - 1) / TB)          // 391
#define RP_BLK   ((N_NODES + 1 + TB - 1) / TB)      // 391
#define FUSED_BLK ((N_NODES + 255) / 256)           // 391 (2 nodes/thread @128thr)
#define SPMM_BLK ((N_NODES + 31) / 32)              // 3125 (R4: 8 threads/row)
#define STATS_G  592
#define STATS_TILE 64
#define N_TILES  ((N_NODES + STATS_TILE - 1) / STATS_TILE)   // 1563

// ---------------- fused: row_ptr build + stats zero + x@W1 ------------------
__global__ void prolog_kernel(const int* __restrict__ row, const float* __restrict__ x,
                              const float* __restrict__ W, float* __restrict__ y) {
    if (blockIdx.x >= NODE_BLK) {
        int t = threadIdx.x;
        if (blockIdx.x == NODE_BLK) {   // zero stats accumulators (first layer)
            if (t < HID * HID) g_M[t] = 0.0;
            if (t < HID) g_sum16[t] = 0.0;
            if (t == 0) g_cnt = 0;
        }
        int i = (blockIdx.x - NODE_BLK) * TB + t;
        if (i > N_NODES) return;
        int lo = 0, hi = N_EDGES;
        while (lo < hi) {
            int mid = (lo + hi) >> 1;
            if (row[mid] < i) lo = mid + 1; else hi = mid;
        }
        g_row_ptr[i] = lo;
        return;
    }
    __shared__ __align__(16) float Ws[DIM * HID];
    for (int i = threadIdx.x; i < DIM * HID; i += TB) Ws[i] = W[i];
    __syncthreads();
    int n = blockIdx.x * TB + threadIdx.x;
    if (n >= N_NODES) return;
    ull acc2[8];
    #pragma unroll
    for (int j = 0; j < 8; j++) acc2[j] = 0ull;
    const float4* xr = reinterpret_cast<const float4*>(x + (size_t)n * DIM);
    #pragma unroll 4
    for (int d4 = 0; d4 < DIM / 4; d4++) {
        float4 xv = xr[d4];
        #pragma unroll
        for (int dd = 0; dd < 4; dd++) {
            float xd = (&xv.x)[dd];
            ull xb = pack2(xd, xd);
            const ulonglong2* wr = reinterpret_cast<const ulonglong2*>(&Ws[(d4 * 4 + dd) * HID]);
            #pragma unroll
            for (int p = 0; p < 4; p++) {
                ulonglong2 w = wr[p];
                acc2[p * 2 + 0] = fma2(xb, w.x, acc2[p * 2 + 0]);
                acc2[p * 2 + 1] = fma2(xb, w.y, acc2[p * 2 + 1]);
            }
        }
    }
    ull* yr = reinterpret_cast<ull*>(y + (size_t)n * HID);
    #pragma unroll
    for (int j = 0; j < 8; j++) yr[j] = acc2[j];
}

// ---------------- 16-wide SpMM (R4 core, verbatim): 8 threads/row -----------
template<bool RELU>
__global__ void spmm16(const float4* __restrict__ h, const float* __restrict__ vals,
                       const int* __restrict__ col, const float4* __restrict__ bias4,
                       float4* __restrict__ out) {
    int t = threadIdx.x;
    int q = t & 3;
    int sub = (t >> 2) & 1;
    int r = blockIdx.x * 32 + (t >> 3);
    if (r >= N_NODES) return;
    int e0 = g_row_ptr[r], e1 = g_row_ptr[r + 1];
    float4 acc = make_float4(0.f, 0.f, 0.f, 0.f);
    int e = e0 + sub * 4;
    while (e + 4 <= e1) {
        int   c0 = col[e],     c1 = col[e + 1],  c2 = col[e + 2],  c3 = col[e + 3];
        float v0 = vals[e],    v1 = vals[e + 1], v2 = vals[e + 2], v3 = vals[e + 3];
        float4 h0 = h[(size_t)c0 * 4 + q];
        float4 h1 = h[(size_t)c1 * 4 + q];
        float4 h2 = h[(size_t)c2 * 4 + q];
        float4 h3 = h[(size_t)c3 * 4 + q];
        acc.x += v0 * h0.x; acc.y += v0 * h0.y; acc.z += v0 * h0.z; acc.w += v0 * h0.w;
        acc.x += v1 * h1.x; acc.y += v1 * h1.y; acc.z += v1 * h1.z; acc.w += v1 * h1.w;
        acc.x += v2 * h2.x; acc.y += v2 * h2.y; acc.z += v2 * h2.z; acc.w += v2 * h2.w;
        acc.x += v3 * h3.x; acc.y += v3 * h3.y; acc.z += v3 * h3.z; acc.w += v3 * h3.w;
        e += 8;
    }
    int eend = min(e + 4, e1);
    for (; e < eend; e++) {
        float v = vals[e];
        float4 hv = h[(size_t)col[e] * 4 + q];
        acc.x += v * hv.x; acc.y += v * hv.y; acc.z += v * hv.z; acc.w += v * hv.w;
    }
    acc.x += __shfl_xor_sync(0xffffffffu, acc.x, 4);
    acc.y += __shfl_xor_sync(0xffffffffu, acc.y, 4);
    acc.z += __shfl_xor_sync(0xffffffffu, acc.z, 4);
    acc.w += __shfl_xor_sync(0xffffffffu, acc.w, 4);
    if (sub == 0) {
        if (RELU) {
            float4 b = bias4[q];
            acc.x = fmaxf(acc.x + b.x, 0.f);
            acc.y = fmaxf(acc.y + b.y, 0.f);
            acc.z = fmaxf(acc.z + b.z, 0.f);
            acc.w = fmaxf(acc.w + b.w, 0.f);
        }
        out[(size_t)r * 4 + q] = acc;
    }
}

// ---------------- stats + BN prep (R7 variant, verbatim) --------------------
__global__ void stats16_bn(const float* __restrict__ agg,
                           const float* __restrict__ W2,
                           const float* __restrict__ gamma,
                           const float* __restrict__ beta) {
    __shared__ __align__(16) float rows[STATS_TILE * HID];
    int t = threadIdx.x;
    int j = t >> 4, k = t & 15;
    float m0 = 0.f, m1 = 0.f, m2 = 0.f, m3 = 0.f;
    float s0 = 0.f, s1 = 0.f, s2 = 0.f, s3 = 0.f;
    for (int tile = blockIdx.x; tile < N_TILES; tile += STATS_G) {
        int r0 = tile * STATS_TILE;
        int nr = min(STATS_TILE, N_NODES - r0);
        __syncthreads();
        if (t < nr * 4)
            reinterpret_cast<float4*>(rows)[t] =
                reinterpret_cast<const float4*>(agg + (size_t)r0 * HID)[t];
        __syncthreads();
        #pragma unroll 2
        for (int rr = 0; rr + 4 <= nr; rr += 4) {
            float aj0 = rows[(rr + 0) * HID + j], ak0 = rows[(rr + 0) * HID + k];
            float aj1 = rows[(rr + 1) * HID + j], ak1 = rows[(rr + 1) * HID + k];
            float aj2 = rows[(rr + 2) * HID + j], ak2 = rows[(rr + 2) * HID + k];
            float aj3 = rows[(rr + 3) * HID + j], ak3 = rows[(rr + 3) * HID + k];
            m0 += aj0 * ak0; m1 += aj1 * ak1; m2 += aj2 * ak2; m3 += aj3 * ak3;
            if (j == 0) { s0 += ak0; s1 += ak1; s2 += ak2; s3 += ak3; }
        }
    }
    atomicAdd(&g_M[t], (double)((m0 + m1) + (m2 + m3)));
    if (j == 0) atomicAdd(&g_sum16[k], (double)((s0 + s1) + (s2 + s3)));

    __threadfence();
    __shared__ unsigned int sIsLast;
    if (t == 0) {
        unsigned int old = atomicAdd(&g_cnt, 1u);
        sIsLast = (old == gridDim.x - 1) ? 1u : 0u;
    }
    __syncthreads();
    if (!sIsLast) return;
    __shared__ float  Mc[HID * HID];
    __shared__ double Ss[HID];
    if (t < HID) Ss[t] = g_sum16[t];
    __syncthreads();
    const double invN = 1.0 / (double)N_NODES;
    {
        double m = g_M[t];
        Mc[t] = (float)(m - Ss[j] * Ss[k] * invN);
    }
    __syncthreads();
    if (t < DIM) {
        float wf[HID];
        #pragma unroll
        for (int kk = 0; kk < HID; kk++) wf[kk] = W2[kk * DIM + t];
        double sn = 0.0;
        #pragma unroll
        for (int kk = 0; kk < HID; kk++) sn += Ss[kk] * (double)wf[kk];
        sn *= invN;
        float q0 = 0.f, q1 = 0.f, q2 = 0.f, q3 = 0.f;
        #pragma unroll
        for (int a = 0; a < HID; a++) {
            float wa = wf[a];
            #pragma unroll
            for (int b = 0; b < HID; b += 4) {
                q0 += Mc[a * HID + b + 0] * (wa * wf[b + 0]);
                q1 += Mc[a * HID + b + 1] * (wa * wf[b + 1]);
                q2 += Mc[a * HID + b + 2] * (wa * wf[b + 2]);
                q3 += Mc[a * HID + b + 3] * (wa * wf[b + 3]);
            }
        }
        float var = ((q0 + q1) + (q2 + q3)) * (float)invN;
        float scale = rsqrtf(fmaxf(var, 0.f) + BN_EPS) * gamma[t];
        g_scale[t] = scale;
        g_shift[t] = beta[t] - (float)sn * scale;   // b2 cancels in (h2-mean)
    }
    __syncthreads();
    g_M[t] = 0.0;
    if (t < HID) g_sum16[t] = 0.0;
    if (t == 0) g_cnt = 0;
}

// ---------------- fused: h1 = relu(bn(agg@W2)) @ W1next ---------------------
// R12-measured-best: 128 threads, TWO nodes per thread (weight LDS shared).
__global__ void __launch_bounds__(FTB)
fused_bn_gemm(const float* __restrict__ agg, const float* __restrict__ W2,
              const float* __restrict__ W1n, float* __restrict__ y) {
    __shared__ __align__(16) float W2s[HID * DIM];
    __shared__ __align__(16) float W1s[DIM * HID];
    __shared__ __align__(16) float scl[DIM];
    __shared__ __align__(16) float sft[DIM];
    int t = threadIdx.x;
    for (int i = t; i < HID * DIM; i += FTB) {
        W2s[i] = W2[i];
        W1s[i] = W1n[i];
    }
    if (t < DIM) { scl[t] = g_scale[t]; sft[t] = g_shift[t]; }
    __syncthreads();
    int n0 = blockIdx.x * 256 + t;
    int n1 = n0 + FTB;
    bool has1 = (n1 < N_NODES);
    if (n0 >= N_NODES) return;
    ull aA[HID], aB[HID];
    {
        const float4* ar = reinterpret_cast<const float4*>(agg + (size_t)n0 * HID);
        #pragma unroll
        for (int k4 = 0; k4 < 4; k4++) {
            float4 v = ar[k4];
            aA[k4*4+0] = pack2(v.x, v.x);
            aA[k4*4+1] = pack2(v.y, v.y);
            aA[k4*4+2] = pack2(v.z, v.z);
            aA[k4*4+3] = pack2(v.w, v.w);
        }
        if (has1) {
            const float4* br = reinterpret_cast<const float4*>(agg + (size_t)n1 * HID);
            #pragma unroll
            for (int k4 = 0; k4 < 4; k4++) {
                float4 v = br[k4];
                aB[k4*4+0] = pack2(v.x, v.x);
                aB[k4*4+1] = pack2(v.y, v.y);
                aB[k4*4+2] = pack2(v.z, v.z);
                aB[k4*4+3] = pack2(v.w, v.w);
            }
        } else {
            #pragma unroll
            for (int k = 0; k < HID; k++) aB[k] = 0ull;
        }
    }
    ull accA[8], accB[8];
    #pragma unroll
    for (int j = 0; j < 8; j++) { accA[j] = 0ull; accB[j] = 0ull; }
    for (int cb = 0; cb < DIM; cb += 4) {
        ull tA0 = 0ull, tA1 = 0ull, tB0 = 0ull, tB1 = 0ull;
        const ulonglong2* w2p = reinterpret_cast<const ulonglong2*>(&W2s[cb]);
        #pragma unroll
        for (int k = 0; k < HID; k++) {
            ulonglong2 w = w2p[k * (DIM / 4)];
            tA0 = fma2(aA[k], w.x, tA0);
            tA1 = fma2(aA[k], w.y, tA1);
            tB0 = fma2(aB[k], w.x, tB0);
            tB1 = fma2(aB[k], w.y, tB1);
        }
        ulonglong2 sc = *reinterpret_cast<const ulonglong2*>(&scl[cb]);
        ulonglong2 sf = *reinterpret_cast<const ulonglong2*>(&sft[cb]);
        tA0 = fma2(tA0, sc.x, sf.x);
        tA1 = fma2(tA1, sc.y, sf.y);
        tB0 = fma2(tB0, sc.x, sf.x);
        tB1 = fma2(tB1, sc.y, sf.y);
        float vA[4], vB[4];
        unpack2(tA0, vA[0], vA[1]); unpack2(tA1, vA[2], vA[3]);
        unpack2(tB0, vB[0], vB[1]); unpack2(tB1, vB[2], vB[3]);
        #pragma unroll
        for (int c = 0; c < 4; c++) {
            vA[c] = fmaxf(vA[c], 0.f);
            vB[c] = fmaxf(vB[c], 0.f);
        }
        #pragma unroll
        for (int c = 0; c < 4; c++) {
            ull vAc = pack2(vA[c], vA[c]);
            ull vBc = pack2(vB[c], vB[c]);
            const ulonglong2* w1p = reinterpret_cast<const ulonglong2*>(&W1s[(cb + c) * HID]);
            #pragma unroll
            for (int p = 0; p < 4; p++) {
                ulonglong2 w = w1p[p];
                accA[p * 2 + 0] = fma2(vAc, w.x, accA[p * 2 + 0]);
                accA[p * 2 + 1] = fma2(vAc, w.y, accA[p * 2 + 1]);
                accB[p * 2 + 0] = fma2(vBc, w.x, accB[p * 2 + 0]);
                accB[p * 2 + 1] = fma2(vBc, w.y, accB[p * 2 + 1]);
            }
        }
    }
    ull* yr0 = reinterpret_cast<ull*>(y + (size_t)n0 * HID);
    #pragma unroll
    for (int j = 0; j < 8; j++) yr0[j] = accA[j];
    if (has1) {
        ull* yr1 = reinterpret_cast<ull*>(y + (size_t)n1 * HID);
        #pragma unroll
        for (int j = 0; j < 8; j++) yr1[j] = accB[j];
    }
}

// ---------------- out[N,40] = agg[N,16] @ W[16,40] + b  (f32x2 packed) ------
__global__ void out_gemm(const float* __restrict__ agg, const float* __restrict__ W,
                         const float* __restrict__ b, float* __restrict__ out) {
    __shared__ __align__(16) float Ws[HID * NCLS];
    __shared__ __align__(16) float bs[NCLS];
    for (int i = threadIdx.x; i < HID * NCLS; i += TB) Ws[i] = W[i];
    if (threadIdx.x < NCLS) bs[threadIdx.x] = b[threadIdx.x];
    __syncthreads();
    int n = blockIdx.x * TB + threadIdx.x;
    if (n >= N_NODES) return;
    ull a2[HID];
    {
        const float4* ar = reinterpret_cast<const float4*>(agg + (size_t)n * HID);
        #pragma unroll
        for (int k4 = 0; k4 < 4; k4++) {
            float4 v = ar[k4];
            a2[k4*4+0] = pack2(v.x, v.x);
            a2[k4*4+1] = pack2(v.y, v.y);
            a2[k4*4+2] = pack2(v.z, v.z);
            a2[k4*4+3] = pack2(v.w, v.w);
        }
    }
    ull o2[NCLS / 2];
    const ull* bp = reinterpret_cast<const ull*>(bs);
    #pragma unroll
    for (int p = 0; p < NCLS / 2; p++) o2[p] = bp[p];
    #pragma unroll
    for (int k = 0; k < HID; k++) {
        const ull* wr = reinterpret_cast<const ull*>(&Ws[k * NCLS]);
        #pragma unroll
        for (int p = 0; p < NCLS / 2; p++)
            o2[p] = fma2(a2[k], wr[p], o2[p]);
    }
    ull* orow = reinterpret_cast<ull*>(out + (size_t)n * NCLS);
    #pragma unroll
    for (int p = 0; p < NCLS / 2; p++) orow[p] = o2[p];
}

// ============================================================================
extern "C" void kernel_launch(void* const* d_in, const int* in_sizes, int n_in,
                              void* d_out, int out_size) {
    const float* x     = (const float*)d_in[0];
    const float* vals  = (const float*)d_in[1];
    const float* W1    = (const float*)d_in[2];   // (3,128,16)
    const float* b1    = (const float*)d_in[3];   // (3,16)
    const float* W2    = (const float*)d_in[4];   // (3,16,128)
    const float* gamma = (const float*)d_in[6];   // (3,128)
    const float* beta  = (const float*)d_in[7];   // (3,128)
    const float* W1f   = (const float*)d_in[8];   // (128,16)
    const float* b1f   = (const float*)d_in[9];   // (16,)
    const float* W2f   = (const float*)d_in[10];  // (16,40)
    const float* b2f   = (const float*)d_in[11];  // (40,)
    const int*   row   = (const int*)d_in[12];
    const int*   col   = (const int*)d_in[13];
    float* out = (float*)d_out;
    // d_in[5] (b2) cancels inside batchnorm.

    float *p_h1, *p_s1, *p_agg;
    cudaGetSymbolAddress((void**)&p_h1,  g_h1);
    cudaGetSymbolAddress((void**)&p_s1,  g_s1);
    cudaGetSymbolAddress((void**)&p_agg, g_agg);

    prolog_kernel<<<NODE_BLK + RP_BLK, TB>>>(row, x, W1, p_h1);

    for (int i = 0; i < 3; i++) {
        spmm16<true><<<SPMM_BLK, TB>>>((const float4*)p_h1, vals, col,
                                       (const float4*)(b1 + i * HID), (float4*)p_s1);
        spmm16<false><<<SPMM_BLK, TB>>>((const float4*)p_s1, vals, col,
                                        nullptr, (float4*)p_agg);
        stats16_bn<<<STATS_G, TB>>>(p_agg, W2 + (size_t)i * HID * DIM,
                                    gamma + i * DIM, beta + i * DIM);
        const float* Wnext = (i < 2) ? (W1 + (size_t)(i + 1) * DIM * HID) : W1f;
        fused_bn_gemm<<<FUSED_BLK, FTB>>>(p_agg, W2 + (size_t)i * HID * DIM, Wnext, p_h1);
    }

    spmm16<true><<<SPMM_BLK, TB>>>((const float4*)p_h1, vals, col,
                                   (const float4*)b1f, (float4*)p_s1);
    spmm16<false><<<SPMM_BLK, TB>>>((const float4*)p_s1, vals, col,
                                    nullptr, (float4*)p_agg);
    out_gemm<<<NODE_BLK, TB>>>(p_agg, W2f, b2f, out);
}